// round 1
// baseline (speedup 1.0000x reference)
#include <cuda_runtime.h>
#include <cstdint>

// Problem constants
#define Bc  4
#define Tc  2048
#define Cc  1024
#define NHc 16
#define HDc 64

// Scratch (no cudaMalloc allowed): Q/K/V in [B*NH, T, HD], Y in [B, T, C]
__device__ float g_q[Bc * NHc * Tc * HDc];
__device__ float g_k[Bc * NHc * Tc * HDc];
__device__ float g_v[Bc * NHc * Tc * HDc];
__device__ float g_y[Bc * Tc * Cc];

// ---------------------------------------------------------------------------
// Tiled SGEMM: C = A @ B + bias.  BM=BN=128, BK=16, 256 threads, 8x8 microtile.
// MODE 0: epilogue scatters qkv into g_q/g_k/g_v ([B*NH, T, HD] layout)
// MODE 1: epilogue writes Out[m*N + n]; A is taken from g_y (attention output)
// ---------------------------------------------------------------------------
constexpr int BM = 128, BN = 128, BK = 16, TM = 8, TN = 8;

template <int MODE>
__global__ __launch_bounds__(256)
void sgemm_kernel(const float* __restrict__ A, const float* __restrict__ Bmat,
                  const float* __restrict__ bias, float* __restrict__ Out,
                  int M, int N, int K)
{
    __shared__ float As[BK][BM];
    __shared__ float Bs[BK][BN];

    const float* Ap = (MODE == 1) ? g_y : A;

    int tid = threadIdx.x;
    int block_m = blockIdx.y * BM;
    int block_n = blockIdx.x * BN;
    int ty = tid >> 4;          // 0..15
    int tx = tid & 15;          // 0..15

    // A tile load mapping: [BM x BK] -> thread loads 2 float4
    int arow = tid >> 2;        // 0..63 (+64 second pass)
    int acol = (tid & 3) * 4;   // 0,4,8,12
    // B tile load mapping: [BK x BN] -> thread loads 2 float4
    int brow = tid >> 5;        // 0..7 (+8 second pass)
    int bcol = (tid & 31) * 4;  // 0..124

    float acc[TM][TN] = {};

    const float* Abase = Ap + (size_t)block_m * K;
    const float* Bbase = Bmat + block_n;

    for (int k0 = 0; k0 < K; k0 += BK) {
#pragma unroll
        for (int i = 0; i < 2; i++) {
            int r = arow + i * 64;
            float4 a4 = *(const float4*)(Abase + (size_t)r * K + k0 + acol);
            As[acol + 0][r] = a4.x;
            As[acol + 1][r] = a4.y;
            As[acol + 2][r] = a4.z;
            As[acol + 3][r] = a4.w;
        }
#pragma unroll
        for (int i = 0; i < 2; i++) {
            int r = brow + i * 8;
            float4 b4 = *(const float4*)(Bbase + (size_t)(k0 + r) * N + bcol);
            *(float4*)&Bs[r][bcol] = b4;
        }
        __syncthreads();

#pragma unroll
        for (int kk = 0; kk < BK; kk++) {
            float ra[TM], rb[TN];
#pragma unroll
            for (int i = 0; i < TM; i++) ra[i] = As[kk][ty * TM + i];
#pragma unroll
            for (int j = 0; j < TN; j++) rb[j] = Bs[kk][tx * TN + j];
#pragma unroll
            for (int i = 0; i < TM; i++)
#pragma unroll
                for (int j = 0; j < TN; j++)
                    acc[i][j] += ra[i] * rb[j];
        }
        __syncthreads();
    }

#pragma unroll
    for (int i = 0; i < TM; i++) {
        int m = block_m + ty * TM + i;
#pragma unroll
        for (int j = 0; j < TN; j++) {
            int n = block_n + tx * TN + j;
            float v = acc[i][j] + bias[n];
            if (MODE == 0) {
                // n in [0, 3C): split into q/k/v, scatter to [B*NH, T, HD]
                int which = n / Cc;
                int c = n - which * Cc;
                int h = c >> 6;        // / HD
                int d = c & 63;        // % HD
                int b = m / Tc;
                int t = m - b * Tc;
                size_t idx = (((size_t)(b * NHc + h)) * Tc + t) * HDc + d;
                float* dst = (which == 0) ? g_q : ((which == 1) ? g_k : g_v);
                dst[idx] = v;
            } else {
                Out[(size_t)m * N + n] = v;
            }
        }
    }
}

// ---------------------------------------------------------------------------
// Flash attention (fp32): one thread per query row, 64-key shared tiles,
// lazy max-rescale so steady state is 128 FMA + 1 exp per key.
// grid = (B*NH, T/128), block = 128 threads.
// ---------------------------------------------------------------------------
constexpr int AROWS = 128;  // queries per block (= threads)
constexpr int KB = 64;      // keys per tile

__global__ __launch_bounds__(128, 2)
void attn_kernel()
{
    __shared__ float Ks[KB][HDc];
    __shared__ float Vs[KB][HDc];

    int bh = blockIdx.x;                       // 0..B*NH-1
    int t  = blockIdx.y * AROWS + threadIdx.x; // query index in sequence

    const float* qp = g_q + ((size_t)bh * Tc + t) * HDc;
    float q[HDc];
#pragma unroll
    for (int d = 0; d < HDc; d++) q[d] = qp[d] * 0.125f;  // 1/sqrt(64)

    float o[HDc] = {};
    float mval = -1e30f, l = 0.f;

    const float* kbase = g_k + (size_t)bh * Tc * HDc;
    const float* vbase = g_v + (size_t)bh * Tc * HDc;

    int kmax = blockIdx.y * AROWS + AROWS - 1;  // last query row in this block

    for (int k0 = 0; k0 <= kmax; k0 += KB) {
        __syncthreads();
        // cooperative load: 64x64 K + V tiles (1024 float4 each)
#pragma unroll
        for (int i = 0; i < 8; i++) {
            int idx = threadIdx.x + i * 128;
            ((float4*)Ks)[idx] = ((const float4*)(kbase + (size_t)k0 * HDc))[idx];
            ((float4*)Vs)[idx] = ((const float4*)(vbase + (size_t)k0 * HDc))[idx];
        }
        __syncthreads();

        int jend = min(KB, t - k0 + 1);   // causal bound (may be <=0)
        for (int j = 0; j < jend; j++) {
            // dot(q, K[j]) with 4 partial sums to break the FMA chain
            float s0 = 0.f, s1 = 0.f, s2 = 0.f, s3 = 0.f;
            const float4* krow = (const float4*)&Ks[j][0];
#pragma unroll
            for (int d4 = 0; d4 < 16; d4++) {
                float4 k4 = krow[d4];
                s0 += q[d4 * 4 + 0] * k4.x;
                s1 += q[d4 * 4 + 1] * k4.y;
                s2 += q[d4 * 4 + 2] * k4.z;
                s3 += q[d4 * 4 + 3] * k4.w;
            }
            float s = (s0 + s1) + (s2 + s3);

            if (s > mval) {  // rare: rescale accumulator
                float corr = __expf(mval - s);
                l *= corr;
#pragma unroll
                for (int d = 0; d < HDc; d++) o[d] *= corr;
                mval = s;
            }
            float p = __expf(s - mval);
            l += p;
            const float4* vrow = (const float4*)&Vs[j][0];
#pragma unroll
            for (int d4 = 0; d4 < 16; d4++) {
                float4 v4 = vrow[d4];
                o[d4 * 4 + 0] += p * v4.x;
                o[d4 * 4 + 1] += p * v4.y;
                o[d4 * 4 + 2] += p * v4.z;
                o[d4 * 4 + 3] += p * v4.w;
            }
        }
    }

    // write to g_y in [B, T, C] layout
    int b = bh / NHc;
    int h = bh - b * NHc;
    float inv_l = 1.f / l;
    float* yp = g_y + ((size_t)b * Tc + t) * Cc + h * HDc;
#pragma unroll
    for (int d = 0; d < HDc; d++) yp[d] = o[d] * inv_l;
}

// ---------------------------------------------------------------------------
// Launch
// ---------------------------------------------------------------------------
extern "C" void kernel_launch(void* const* d_in, const int* in_sizes, int n_in,
                              void* d_out, int out_size)
{
    const float* x      = (const float*)d_in[0];  // [B,T,C]
    const float* W_attn = (const float*)d_in[1];  // [C,3C]
    const float* b_attn = (const float*)d_in[2];  // [3C]
    const float* W_proj = (const float*)d_in[3];  // [C,C]
    const float* b_proj = (const float*)d_in[4];  // [C]
    float* out = (float*)d_out;                   // [B,T,C]

    // 1) QKV GEMM: [8192,1024] @ [1024,3072] + bias -> scatter to g_q/g_k/g_v
    {
        dim3 grid((3 * Cc) / BN, (Bc * Tc) / BM);
        sgemm_kernel<0><<<grid, 256>>>(x, W_attn, b_attn, nullptr,
                                       Bc * Tc, 3 * Cc, Cc);
    }
    // 2) causal flash attention -> g_y [B,T,C]
    {
        dim3 grid(Bc * NHc, Tc / AROWS);
        attn_kernel<<<grid, 128>>>();
    }
    // 3) projection GEMM: g_y @ W_proj + bias -> out
    {
        dim3 grid(Cc / BN, (Bc * Tc) / BM);
        sgemm_kernel<1><<<grid, 256>>>(nullptr, W_proj, b_proj, out,
                                       Bc * Tc, Cc, Cc);
    }
}